// round 1
// baseline (speedup 1.0000x reference)
#include <cuda_runtime.h>
#include <cstddef>

// ---------------------------------------------------------------------------
// DWReg2DDecode3D: grid_sample -> upsample GEMM -> 4x(pool -> spiral dsconv
// -> relu) -> head dsconv.  B=16, NV={12544,6272,3136,1568,784}, SPIRAL=9.
// ---------------------------------------------------------------------------

#define B 16
#define SP 9

// scratch (device globals; no allocations allowed)
__device__ float g_gs[B * 64 * 256];          // grid-sampled feats (b,p,c)
__device__ float g_bufB[12845056];            // conv outputs / x0  (max 16*3136*256)
__device__ float g_bufA[25690112];            // pool outputs       (max 16*6272*256)

// ---------------- packed f32x2 helpers (sm_10x FFMA2 path) -----------------
__device__ __forceinline__ void fma2(unsigned long long& d,
                                     unsigned long long a,
                                     unsigned long long b) {
    asm("fma.rn.f32x2 %0, %1, %2, %0;" : "+l"(d) : "l"(a), "l"(b));
}
__device__ __forceinline__ unsigned long long dup2(float x) {
    unsigned long long u;
    asm("mov.b64 %0, {%1, %1};" : "=l"(u) : "f"(x));
    return u;
}
__device__ __forceinline__ float2 unpk(unsigned long long u) {
    float2 r;
    asm("mov.b64 {%0, %1}, %2;" : "=f"(r.x), "=f"(r.y) : "l"(u));
    return r;
}

// ---------------- grid sample (bilinear, align_corners, zero pad) ----------
__global__ void __launch_bounds__(256)
k_gridsample(const float* __restrict__ uv, const float* __restrict__ feat,
             float* __restrict__ gs)
{
    const int b = blockIdx.x, c = threadIdx.x;
    const float* fb = feat + ((size_t)b * 256 + c) * 16;
    for (int p = 0; p < 64; ++p) {
        float gx = (uv[((size_t)b * 64 + p) * 2 + 0] - 0.5f) * 2.f;
        float gy = (uv[((size_t)b * 64 + p) * 2 + 1] - 0.5f) * 2.f;
        gx = fminf(fmaxf(gx, -1.f), 1.f);
        gy = fminf(fmaxf(gy, -1.f), 1.f);
        float x = (gx + 1.f) * 0.5f * 3.f;
        float y = (gy + 1.f) * 0.5f * 3.f;
        float x0f = floorf(x), y0f = floorf(y);
        int x0 = (int)x0f, y0 = (int)y0f;
        int x1 = x0 + 1, y1 = y0 + 1;
        float fx = x - x0f, fy = y - y0f;
        float wa = (1.f - fx) * (1.f - fy);
        float wb = (1.f - fx) * fy;
        float wc = fx * (1.f - fy);
        float wd = fx * fy;
        float Ia = (x0 >= 0 && x0 < 4 && y0 >= 0 && y0 < 4) ? fb[y0 * 4 + x0] : 0.f;
        float Ib = (x0 >= 0 && x0 < 4 && y1 >= 0 && y1 < 4) ? fb[y1 * 4 + x0] : 0.f;
        float Ic = (x1 >= 0 && x1 < 4 && y0 >= 0 && y0 < 4) ? fb[y0 * 4 + x1] : 0.f;
        float Id = (x1 >= 0 && x1 < 4 && y1 >= 0 && y1 < 4) ? fb[y1 * 4 + x1] : 0.f;
        gs[((size_t)b * 64 + p) * 256 + c] = Ia * wa + Ib * wb + Ic * wc + Id * wd;
    }
}

// ---------------- upsample GEMM: out[b,v,c] = sum_p up[v,p]*gs[b,p,c] ------
__global__ void __launch_bounds__(256)
k_upsample(const float* __restrict__ up, const float* __restrict__ gs,
           float* __restrict__ out)
{
    constexpr int VT = 16;
    __shared__ float up_s[VT][64];
    const int b = blockIdx.y, v0 = blockIdx.x * VT, c = threadIdx.x;
    for (int t = threadIdx.x; t < VT * 64; t += 256)
        up_s[t / 64][t % 64] = up[(size_t)(v0 + t / 64) * 64 + (t % 64)];
    __syncthreads();
    float acc[VT];
#pragma unroll
    for (int i = 0; i < VT; ++i) acc[i] = 0.f;
    for (int p = 0; p < 64; ++p) {
        float g = gs[((size_t)b * 64 + p) * 256 + c];
#pragma unroll
        for (int i = 0; i < VT; ++i) acc[i] = fmaf(up_s[i][p], g, acc[i]);
    }
#pragma unroll
    for (int i = 0; i < VT; ++i)
        out[((size_t)b * 784 + v0 + i) * 256 + c] = acc[i];
}

// ---------------- mesh up-pool: out[b,n,c] = sum_k x[b,col[3n+k],c]*val ----
template <int Ci>
__global__ void __launch_bounds__(256)
k_pool(const float4* __restrict__ x, const int* __restrict__ col,
       const float* __restrict__ val, float4* __restrict__ out,
       int Nin, int Nout)
{
    constexpr int CQ = Ci / 4;
    constexpr int VPB = 256 / CQ;
    const int b = blockIdx.y;
    const int n = blockIdx.x * VPB + threadIdx.x / CQ;
    const int cq = threadIdx.x % CQ;
    if (n >= Nout) return;
    const int c0 = col[3 * n + 0], c1 = col[3 * n + 1], c2 = col[3 * n + 2];
    const float v0 = val[3 * n + 0], v1 = val[3 * n + 1], v2 = val[3 * n + 2];
    const float4* xb = x + (size_t)b * Nin * CQ;
    float4 a = xb[(size_t)c0 * CQ + cq];
    float4 bb = xb[(size_t)c1 * CQ + cq];
    float4 cc = xb[(size_t)c2 * CQ + cq];
    float4 r;
    r.x = a.x * v0 + bb.x * v1 + cc.x * v2;
    r.y = a.y * v0 + bb.y * v1 + cc.y * v2;
    r.z = a.z * v0 + bb.z * v1 + cc.z * v2;
    r.w = a.w * v0 + bb.w * v1 + cc.w * v2;
    out[((size_t)b * Nout + n) * CQ + cq] = r;
}

// ---------------- fused spiral dsconv: gather*dw then @pw (+relu) ----------
template <int Ci, int Co, bool RELU>
__global__ void __launch_bounds__(256)
k_dsconv(const float* __restrict__ x, const int* __restrict__ idx,
         const float* __restrict__ dw, const float* __restrict__ pw,
         float* __restrict__ out, int N)
{
    constexpr int VT = 32;               // vertices per block
    constexpr int KK = 16;               // k-chunk for pw tiles
    constexpr int CO_T = Co / 4;         // threads along co (4 co each)
    constexpr int V_T = 256 / CO_T;      // threads along v
    constexpr int VPT = VT / V_T;        // v per thread
    constexpr int PWB = KK * Co * 4;
    constexpr int IDB = VT * SP * 4;
    constexpr int UBYTES = (PWB > IDB) ? PWB : IDB;

    __shared__ float y_s[VT][Ci];
    __shared__ __align__(16) char u_smem[UBYTES];   // idx_s (phase A) / pw tile (phase B)
    float* pwf = reinterpret_cast<float*>(u_smem);
    int* idx_s = reinterpret_cast<int*>(u_smem);

    const int b = blockIdx.y;
    const int n0 = blockIdx.x * VT;
    const int tid = threadIdx.x;

    for (int t = tid; t < VT * SP; t += 256)
        idx_s[t] = idx[(size_t)(n0 + t / SP) * SP + (t % SP)];
    __syncthreads();

    // ---- phase A: y_s[v][ci] = sum_s x[b, idx[v,s], ci] * dw[ci,s] ----
    {
        constexpr int CREP = 256 / Ci;
        constexpr int VCH = VT / CREP;
        const int ci = tid & (Ci - 1);
        const int vlo = (tid / Ci) * VCH;
        float dwr[SP];
#pragma unroll
        for (int s = 0; s < SP; ++s) dwr[s] = __ldg(&dw[(size_t)ci * SP + s]);
        const float* xb = x + ((size_t)b * N) * Ci + ci;
#pragma unroll 4
        for (int v = vlo; v < vlo + VCH; ++v) {
            float acc = 0.f;
#pragma unroll
            for (int s = 0; s < SP; ++s)
                acc = fmaf(xb[(size_t)idx_s[v * SP + s] * Ci], dwr[s], acc);
            y_s[v][ci] = acc;
        }
    }

    // ---- phase B: out = y_s @ pw, packed f32x2 FMAs ----
    const int co_t = tid % CO_T;
    const int v_t = tid / CO_T;
    const int co0 = co_t * 4;

    unsigned long long acc[VPT][2];
#pragma unroll
    for (int i = 0; i < VPT; ++i) { acc[i][0] = 0ull; acc[i][1] = 0ull; }

    for (int kk = 0; kk < Ci; kk += KK) {
        __syncthreads();
#pragma unroll
        for (int t = tid; t < KK * Co; t += 256)
            pwf[t] = pw[(size_t)kk * Co + t];
        __syncthreads();
#pragma unroll
        for (int k = 0; k < KK; ++k) {
            const unsigned long long* pq =
                reinterpret_cast<const unsigned long long*>(pwf + k * Co + co0);
            const unsigned long long p01 = pq[0];
            const unsigned long long p23 = pq[1];
#pragma unroll
            for (int vi = 0; vi < VPT; ++vi) {
                unsigned long long yy = dup2(y_s[v_t * VPT + vi][kk + k]);
                fma2(acc[vi][0], yy, p01);
                fma2(acc[vi][1], yy, p23);
            }
        }
    }

#pragma unroll
    for (int vi = 0; vi < VPT; ++vi) {
        float2 r01 = unpk(acc[vi][0]);
        float2 r23 = unpk(acc[vi][1]);
        float4 o = make_float4(r01.x, r01.y, r23.x, r23.y);
        if (RELU) {
            o.x = fmaxf(o.x, 0.f); o.y = fmaxf(o.y, 0.f);
            o.z = fmaxf(o.z, 0.f); o.w = fmaxf(o.w, 0.f);
        }
        const int n = n0 + v_t * VPT + vi;
        *reinterpret_cast<float4*>(out + ((size_t)b * N + n) * Co + co0) = o;
    }
}

// ---------------- head: Ci=64 -> Co=3, no relu -----------------------------
__global__ void __launch_bounds__(256)
k_head(const float* __restrict__ x, const int* __restrict__ idx,
       const float* __restrict__ dw, const float* __restrict__ pw,
       float* __restrict__ out, int N)
{
    constexpr int Ci = 64;
    constexpr int VT = 32;
    __shared__ float y_s[VT][Ci];
    __shared__ float pw_s[Ci * 3];
    __shared__ int idx_s[VT * SP];
    const int b = blockIdx.y, n0 = blockIdx.x * VT, tid = threadIdx.x;

    if (tid < Ci * 3) pw_s[tid] = pw[tid];
    for (int t = tid; t < VT * SP; t += 256)
        idx_s[t] = idx[(size_t)(n0 + t / SP) * SP + (t % SP)];
    __syncthreads();

    {
        const int ci = tid & (Ci - 1);
        const int vlo = (tid / Ci) * (VT / 4);
        float dwr[SP];
#pragma unroll
        for (int s = 0; s < SP; ++s) dwr[s] = __ldg(&dw[(size_t)ci * SP + s]);
        const float* xb = x + ((size_t)b * N) * Ci + ci;
#pragma unroll 4
        for (int v = vlo; v < vlo + VT / 4; ++v) {
            float acc = 0.f;
#pragma unroll
            for (int s = 0; s < SP; ++s)
                acc = fmaf(xb[(size_t)idx_s[v * SP + s] * Ci], dwr[s], acc);
            y_s[v][ci] = acc;
        }
    }
    __syncthreads();

    if (tid < VT * 3) {
        const int v = tid / 3, co = tid % 3;
        float acc = 0.f;
#pragma unroll
        for (int ci = 0; ci < Ci; ++ci)
            acc = fmaf(y_s[v][ci], pw_s[ci * 3 + co], acc);
        out[((size_t)b * N + n0 + v) * 3 + co] = acc;
    }
}

// ---------------------------------------------------------------------------
extern "C" void kernel_launch(void* const* d_in, const int* in_sizes, int n_in,
                              void* d_out, int out_size)
{
    const float* uv   = (const float*)d_in[0];
    const float* feat = (const float*)d_in[1];
    const float* up   = (const float*)d_in[2];
    const float* dw0  = (const float*)d_in[3];
    const float* pw0  = (const float*)d_in[4];
    const float* dw1  = (const float*)d_in[5];
    const float* pw1  = (const float*)d_in[6];
    const float* dw2  = (const float*)d_in[7];
    const float* pw2  = (const float*)d_in[8];
    const float* dw3  = (const float*)d_in[9];
    const float* pw3  = (const float*)d_in[10];
    const float* dwh  = (const float*)d_in[11];
    const float* pwh  = (const float*)d_in[12];

    // Resolve input ordering ambiguity: reference-signature order puts
    // up_val_0 (3*12544=37632) at index 13; setup-dict order puts sp_idx_0
    // (12544*9=112896) there.
    const float *upv0, *upv1, *upv2, *upv3;
    const int *spi0, *spi1, *spi2, *spi3, *upc0, *upc1, *upc2, *upc3;
    if (in_sizes[13] == 37632) {
        upv0 = (const float*)d_in[13]; upv1 = (const float*)d_in[14];
        upv2 = (const float*)d_in[15]; upv3 = (const float*)d_in[16];
        spi0 = (const int*)d_in[17]; spi1 = (const int*)d_in[18];
        spi2 = (const int*)d_in[19]; spi3 = (const int*)d_in[20];
        upc0 = (const int*)d_in[21]; upc1 = (const int*)d_in[22];
        upc2 = (const int*)d_in[23]; upc3 = (const int*)d_in[24];
    } else {
        spi0 = (const int*)d_in[13]; upc0 = (const int*)d_in[14]; upv0 = (const float*)d_in[15];
        spi1 = (const int*)d_in[16]; upc1 = (const int*)d_in[17]; upv1 = (const float*)d_in[18];
        spi2 = (const int*)d_in[19]; upc2 = (const int*)d_in[20]; upv2 = (const float*)d_in[21];
        spi3 = (const int*)d_in[22]; upc3 = (const int*)d_in[23]; upv3 = (const float*)d_in[24];
    }

    float *gsP, *bufA, *bufB;
    cudaGetSymbolAddress((void**)&gsP, g_gs);
    cudaGetSymbolAddress((void**)&bufA, g_bufA);
    cudaGetSymbolAddress((void**)&bufB, g_bufB);
    float* outp = (float*)d_out;

    // 1) grid sample -> gs (b,64,256)
    k_gridsample<<<B, 256>>>(uv, feat, gsP);
    // 2) upsample GEMM -> bufB (b,784,256)
    k_upsample<<<dim3(49, B), 256>>>(up, gsP, bufB);

    // stage 0: pool 784->1568 (col_3/val_3), dsconv idx_3 dw0/pw0 (256->256)
    k_pool<256><<<dim3(1568 / 4, B), 256>>>((const float4*)bufB, upc3, upv3,
                                            (float4*)bufA, 784, 1568);
    k_dsconv<256, 256, true><<<dim3(1568 / 32, B), 256>>>(bufA, spi3, dw0, pw0, bufB, 1568);

    // stage 1: pool 1568->3136, dsconv idx_2 dw1/pw1 (256->256)
    k_pool<256><<<dim3(3136 / 4, B), 256>>>((const float4*)bufB, upc2, upv2,
                                            (float4*)bufA, 1568, 3136);
    k_dsconv<256, 256, true><<<dim3(3136 / 32, B), 256>>>(bufA, spi2, dw1, pw1, bufB, 3136);

    // stage 2: pool 3136->6272, dsconv idx_1 dw2/pw2 (256->128)
    k_pool<256><<<dim3(6272 / 4, B), 256>>>((const float4*)bufB, upc1, upv1,
                                            (float4*)bufA, 3136, 6272);
    k_dsconv<256, 128, true><<<dim3(6272 / 32, B), 256>>>(bufA, spi1, dw2, pw2, bufB, 6272);

    // stage 3: pool 6272->12544 (Ci=128), dsconv idx_0 dw3/pw3 (128->64)
    k_pool<128><<<dim3(12544 / 8, B), 256>>>((const float4*)bufB, upc0, upv0,
                                             (float4*)bufA, 6272, 12544);
    k_dsconv<128, 64, true><<<dim3(12544 / 32, B), 256>>>(bufA, spi0, dw3, pw3, bufB, 12544);

    // head: Ci=64 -> 3, no relu
    k_head<<<dim3(12544 / 32, B), 256>>>(bufB, spi0, dwh, pwh, outp, 12544);
}